// round 2
// baseline (speedup 1.0000x reference)
#include <cuda_runtime.h>
#include <cstdint>

// ---------------------------------------------------------------------------
// VMD on GB300: persistent-loop + Stockham radix-4 FFT
//   T = 2^20, K = 3, 50 iterations.
// ---------------------------------------------------------------------------

#define T_N     (1 << 20)
#define T_MASK  (T_N - 1)
#define T_HALF  (1 << 19)
#define T_QTR   (T_N >> 2)

#define NBLK    128
#define NTHR    512
#define EPT     16                    // elements per thread
#define CHUNK   (NTHR * EPT)          // 8192 per block

#define ALPHA_C 2000.0f
#define TAU_C   1e-7f
#define TAU2_C  1e-14f
#define TOL_C   1e-6f

#define SMEM_BYTES (2 * CHUNK * 8 + 16 * 8 * 4)   // two lam buffers + reduce area

// ------------------------- device global scratch ---------------------------
__device__ float2   g_bufA[3 * T_N];
__device__ float2   g_bufB[3 * T_N];
__device__ float2   g_tw[T_N];
__device__ float    g_part[2 * NBLK * 8];
__device__ unsigned g_bar_cnt;
__device__ unsigned g_bar_epoch;

// ------------------------------ helpers ------------------------------------
__device__ __forceinline__ float2 cmulf(float ux, float uy, float2 w) {
    return make_float2(fmaf(ux, w.x, -uy * w.y), fmaf(ux, w.y, uy * w.x));
}

// s_k = 1/(1 + alpha*denom_k) for the 3 modes with ONE rcp.approx + Newton.
__device__ __forceinline__ void mode_scales(float f, float w0, float w1, float w2,
                                            float& s0, float& s1, float& s2) {
    float e0 = f - w0, e1 = f - w1, e2 = f - w2;
    float d0 = e0 * e0, d1 = e1 * e1, d2 = e2 * e2;
    float A0 = fmaf(ALPHA_C, d0 + d1 + TAU2_C, 1.0f);
    float A1 = fmaf(ALPHA_C, d0 + d1 + d2 + TAU2_C, 1.0f);
    float A2 = fmaf(ALPHA_C, d1 + d2 + TAU2_C, 1.0f);
    float p01 = A0 * A1, p12 = A1 * A2, p02 = A0 * A2;
    float p = p01 * A2;
    float r;
    asm("rcp.approx.f32 %0, %1;" : "=f"(r) : "f"(p));
    r = r * fmaf(-p, r, 2.0f);                 // one Newton step
    s0 = r * p12; s1 = r * p02; s2 = r * p01;
}

// Sense-reversing grid barrier (all NBLK blocks co-resident: 1 CTA/SM by smem)
__device__ __forceinline__ void gbar(unsigned* ep) {
    __syncthreads();
    if (threadIdx.x == 0) {
        unsigned target = ++(*ep);
        unsigned prev = atomicAdd(&g_bar_cnt, 1u);
        if (prev == NBLK - 1) {
            g_bar_cnt = 0u;
            __threadfence();
            atomicExch(&g_bar_epoch, target);
        } else {
            while (*((volatile unsigned*)&g_bar_epoch) < target) { }
            __threadfence();
        }
    }
    __syncthreads();
}

// ------------------------------ kernels ------------------------------------
__global__ void tw_kernel() {
    int j = blockIdx.x * blockDim.x + threadIdx.x;
    float ang = -(float)j * (2.0f / (float)T_N);   // exact: -j * 2^-19
    float s, c;
    sincospif(ang, &s, &c);
    g_tw[j] = make_float2(c, s);                   // e^{-2*pi*i*j/T}
}

__global__ void prep_kernel(const float* __restrict__ x) {
    int i = blockIdx.x * blockDim.x + threadIdx.x;
    g_bufA[i] = make_float2(x[i], 0.0f);
    if (i == 0) { g_bar_cnt = 0u; g_bar_epoch = 0u; }
}

// One radix-4 DIF Stockham pass. ab==0: A->B, ab==1: B->A. grid.y = batch.
__global__ void fft_pass(int logs, int ab) {
    int t = blockIdx.x * blockDim.x + threadIdx.x;      // 0 .. T/4-1
    long off = (long)blockIdx.y * T_N;
    const float2* __restrict__ src = (ab ? g_bufB : g_bufA) + off;
    float2* __restrict__ dst       = (ab ? g_bufA : g_bufB) + off;

    int s  = 1 << logs;
    int q  = t & (s - 1);
    int ps = t - q;                                     // p*s  (< T/4)

    float2 a = src[t], b = src[t + T_QTR], c = src[t + 2 * T_QTR], d = src[t + 3 * T_QTR];
    float2 w1 = g_tw[ps], w2 = g_tw[2 * ps], w3 = g_tw[3 * ps];

    float apcx = a.x + c.x, apcy = a.y + c.y;
    float amcx = a.x - c.x, amcy = a.y - c.y;
    float bpdx = b.x + d.x, bpdy = b.y + d.y;
    float bmdx = b.x - d.x, bmdy = b.y - d.y;

    int ob = t + 3 * ps;                                // q + 4*p*s
    dst[ob]         = make_float2(apcx + bpdx, apcy + bpdy);
    dst[ob + s]     = cmulf(amcx + bmdy, amcy - bmdx, w1);   // (a-c) - i(b-d)
    dst[ob + 2 * s] = cmulf(apcx - bpdx, apcy - bpdy, w2);
    dst[ob + 3 * s] = cmulf(amcx - bmdy, amcy + bmdx, w3);   // (a-c) + i(b-d)
}

// Persistent kernel: 50 VMD iterations entirely in SMEM/registers.
// Reads F = FFT(x) from g_bufA (fftshift via indexing);
// writes conj(ifftshift(u_hat_k)) for k=0..2 into g_bufB.
__global__ void __launch_bounds__(NTHR, 1) vmd_loop(const float* __restrict__ om_init) {
    extern __shared__ float sraw[];
    float2* lamA = (float2*)sraw;
    float2* lamB = lamA + CHUNK;
    float*  red  = (float*)(lamB + CHUNK);

    const int tid  = threadIdx.x;
    const int blk  = blockIdx.x;
    const int base = blk * CHUNK + tid;
    const float invT = 1.0f / (float)T_N;
    const float fstep = 512.0f * invT;
    const float fbase = (float)base * invT - 0.5f;

    // Load f_hat (shifted) into registers; zero lambda (iteration-0 buffer).
    float2 fh[EPT];
#pragma unroll
    for (int j = 0; j < EPT; j++) {
        int i = base + j * NTHR;
        fh[j] = g_bufA[(i + T_HALF) & T_MASK];
        lamA[tid + j * NTHR] = make_float2(0.0f, 0.0f);
    }

    float om0 = om_init[0], om1 = om_init[1], om2 = om_init[2];
    float op0 = om0, op1 = om1, op2 = om2;
    unsigned epoch = 0;
    float fo0 = om0, fo1 = om1, fo2 = om2;
    int fpar = 1;
    bool fin = false;

    for (int n = 0; n < 50 && !fin; n++) {
        float2* lamC = (n & 1) ? lamB : lamA;   // holds lam^(n)
        float2* lamN = (n & 1) ? lamA : lamB;   // holds lam^(n-1); gets lam^(n+1)
        const bool chk = (n > 0) && (n % 10 == 0);
        const int par = n & 1;

        float acc[8] = {0, 0, 0, 0, 0, 0, 0, 0};

#pragma unroll
        for (int j = 0; j < EPT; j++) {
            int idx = tid + j * NTHR;
            float f = fbase + (float)j * fstep;

            float s0, s1, s2;
            mode_scales(f, om0, om1, om2, s0, s1, s2);

            float2 lm = lamC[idx];
            float cr = fmaf(-0.5f, lm.x, fh[j].x);
            float ci = fmaf(-0.5f, lm.y, fh[j].y);
            float m2 = fmaf(cr, cr, ci * ci);

            float q0 = s0 * s0 * m2, q1 = s1 * s1 * m2, q2 = s2 * s2 * m2;
            acc[0] = fmaf(f, q0, acc[0]);
            acc[1] = fmaf(f, q1, acc[1]);
            acc[2] = fmaf(f, q2, acc[2]);
            acc[3] += q0; acc[4] += q1; acc[5] += q2;

            if (chk) {
                float s0p, s1p, s2p;
                mode_scales(f, op0, op1, op2, s0p, s1p, s2p);
                float2 lp = lamN[idx];                       // lam^(n-1)
                float cpr = fmaf(-0.5f, lp.x, fh[j].x);
                float cpi = fmaf(-0.5f, lp.y, fh[j].y);
                float er0 = cr * s0 - cpr * s0p, ei0 = ci * s0 - cpi * s0p;
                float er1 = cr * s1 - cpr * s1p, ei1 = ci * s1 - cpi * s1p;
                float er2 = cr * s2 - cpr * s2p, ei2 = ci * s2 - cpi * s2p;
                acc[6] += er0 * er0 + ei0 * ei0 + er1 * er1 + ei1 * ei1
                        + er2 * er2 + ei2 * ei2;
                float m2p = cpr * cpr + cpi * cpi;
                acc[7] = fmaf(m2p, s0p * s0p + s1p * s1p + s2p * s2p, acc[7]);
            }

            float ss = s0 + s1 + s2;
            float ur = fmaf(cr, ss, -fh[j].x);
            float ui = fmaf(ci, ss, -fh[j].y);
            lamN[idx] = make_float2(fmaf(TAU_C, ur, lm.x), fmaf(TAU_C, ui, lm.y));
        }

        // ---- block reduce (warp shuffles -> smem -> 8 slots) ----
        unsigned wid = tid >> 5, lane = tid & 31;
#pragma unroll
        for (int k = 0; k < 8; k++) {
            float v = acc[k];
#pragma unroll
            for (int o = 16; o > 0; o >>= 1) v += __shfl_down_sync(0xffffffffu, v, o);
            if (lane == 0) red[wid * 8 + k] = v;
        }
        __syncthreads();
        if (tid < 8) {
            float s = 0.0f;
#pragma unroll
            for (int w = 0; w < 16; w++) s += red[w * 8 + tid];
            g_part[par * NBLK * 8 + blk * 8 + tid] = s;
            __threadfence();
        }

        gbar(&epoch);

        // ---- cross-block sums (deterministic order, L1-bypass loads) ----
        if (tid < 8) {
            float s = 0.0f;
            const float* pp = g_part + par * NBLK * 8 + tid;
#pragma unroll 8
            for (int b = 0; b < NBLK; b++) s += __ldcg(pp + b * 8);
            red[tid] = s;
        }
        __syncthreads();
        float wn0 = red[0] / red[3];
        float wn1 = red[1] / red[4];
        float wn2 = red[2] / red[5];
        bool brk = false;
        if (chk) {
            float ud = red[6] / red[7];
            float od = (fabsf(wn0 - wn2) + fabsf(wn1 - wn0) + fabsf(wn2 - wn1)) * (1.0f / 3.0f);
            brk = (ud < TOL_C) && (od < TOL_C);
        }
        __syncthreads();   // protect red[] before next iteration overwrites it

        if (brk) {
            fo0 = om0; fo1 = om1; fo2 = om2;   // omega entering this iteration
            fpar = n & 1;                      // lam^(n) lives in buf(n&1)
            fin = true;
        } else {
            op0 = om0; op1 = om1; op2 = om2;
            om0 = wn0; om1 = wn1; om2 = wn2;
        }
    }
    if (!fin) { fo0 = op0; fo1 = op1; fo2 = op2; fpar = 1; }  // omega^(49), lam^(49)

    // ---- final u_hat: write conj(ifftshift(u_k)) into g_bufB[k*T + ...] ----
    float2* lamF = fpar ? lamB : lamA;
#pragma unroll
    for (int j = 0; j < EPT; j++) {
        int idx = tid + j * NTHR;
        int i = base + j * NTHR;
        float f = fbase + (float)j * fstep;
        float s0, s1, s2;
        mode_scales(f, fo0, fo1, fo2, s0, s1, s2);
        float2 lm = lamF[idx];
        float cr = fmaf(-0.5f, lm.x, fh[j].x);
        float ci = fmaf(-0.5f, lm.y, fh[j].y);
        int jd = (i + T_HALF) & T_MASK;
        g_bufB[jd]             = make_float2(cr * s0, -(ci * s0));
        g_bufB[T_N + jd]       = make_float2(cr * s1, -(ci * s1));
        g_bufB[2 * T_N + jd]   = make_float2(cr * s2, -(ci * s2));
    }
}

// out = real(fft(conj(v)))/T  ==  real(ifft(v))
__global__ void out_kernel(float* __restrict__ out) {
    int i = blockIdx.x * blockDim.x + threadIdx.x;
    out[i] = g_bufB[i].x * (1.0f / (float)T_N);
}

// ------------------------------ launcher -----------------------------------
extern "C" void kernel_launch(void* const* d_in, const int* in_sizes, int n_in,
                              void* d_out, int out_size) {
    (void)in_sizes; (void)n_in; (void)out_size;
    const float* x  = (const float*)d_in[0];
    const float* om = (const float*)d_in[1];
    float* out = (float*)d_out;

    cudaFuncSetAttribute((const void*)vmd_loop,
                         cudaFuncAttributeMaxDynamicSharedMemorySize, SMEM_BYTES);

    tw_kernel<<<T_N / 256, 256>>>();
    prep_kernel<<<T_N / 256, 256>>>(x);

    // Forward FFT of x: 10 radix-4 passes, A->B->A...; result lands in bufA.
    int ab = 0;
    for (int p = 0; p < 10; p++) {
        fft_pass<<<dim3(T_QTR / 256, 1), 256>>>(2 * p, ab);
        ab ^= 1;
    }

    // 50 VMD iterations; writes conj(ifftshift(u_hat)) for 3 modes into bufB.
    vmd_loop<<<NBLK, NTHR, SMEM_BYTES>>>(om);

    // Forward FFT of conj(v), batch of 3: B->A->B...; result lands in bufB.
    ab = 1;
    for (int p = 0; p < 10; p++) {
        fft_pass<<<dim3(T_QTR / 256, 3), 256>>>(2 * p, ab);
        ab ^= 1;
    }

    out_kernel<<<(3 * T_N) / 256, 256>>>(out);
}

// round 3
// speedup vs baseline: 1.3671x; 1.3671x over previous
#include <cuda_runtime.h>
#include <cstdint>

// ---------------------------------------------------------------------------
// VMD on GB300, round 3:
//   - FFT: four-step 1024x1024 decomposition, 2 smem kernels per FFT
//   - vmd_loop: 147 persistent blocks (146x7168 + 1x2048), grid barrier
// ---------------------------------------------------------------------------

#define T_N     (1 << 20)
#define T_MASK  (T_N - 1)
#define T_HALF  (1 << 19)

#define NBLK    147
#define NTHR    512
#define EPT_F   14                    // full blocks: 512*14 = 7168 elems
#define EPT_T   4                     // tail block:  512*4  = 2048 elems
#define CHUNK   (NTHR * EPT_F)        // 7168

#define ALPHA_C 2000.0f
#define TAU_C   1e-7f
#define TAU2_C  1e-14f
#define TOL_C   1e-6f

#define VSMEM   (2 * CHUNK * 8 + 16 * 8 * 4)

// ---- FFT geometry: N = 1024 x 1024 ----
#define FN      1024
#define TA      8                     // columns (or rows) per block
#define FTHR    512
#define CSTR    1028                  // smem column stride (float2), pad 4
#define FBLK    (FN / TA)             // 128 blocks per batch
#define F_SMEM  ((2 * TA * CSTR + 2 * 1024) * 8)   // ping+pong + 2 tables

// ------------------------- device global scratch ---------------------------
__device__ float2   g_bufA[3 * T_N];
__device__ float2   g_bufB[3 * T_N];
__device__ float2   g_tw1k[1024];     // e^{-2pi i j / 1024}
__device__ float2   g_twfn[1024];     // e^{-2pi i j / 2^20}
__device__ float    g_part[2 * NBLK * 8];
__device__ unsigned g_bar_cnt;
__device__ unsigned g_bar_epoch;

// ------------------------------ helpers ------------------------------------
__device__ __forceinline__ float2 cmulf(float ux, float uy, float2 w) {
    return make_float2(fmaf(ux, w.x, -uy * w.y), fmaf(ux, w.y, uy * w.x));
}
__device__ __forceinline__ float2 cmul2(float2 a, float2 b) {
    return make_float2(fmaf(a.x, b.x, -a.y * b.y), fmaf(a.x, b.y, a.y * b.x));
}

// XOR swizzle on low 4 bits using bits [4:7] (bijective): breaks the 8-way
// bank conflicts of the low-stride Stockham stages down to <=4-way.
__device__ __forceinline__ int swz(int m) {
    int h = (m >> 4) & 15;
    return m ^ (h ^ ((h << 1) & 15));
}

// s_k = 1/(1 + alpha*denom_k) for the 3 modes with ONE rcp.approx + Newton.
__device__ __forceinline__ void mode_scales(float f, float w0, float w1, float w2,
                                            float& s0, float& s1, float& s2) {
    float e0 = f - w0, e1 = f - w1, e2 = f - w2;
    float d0 = e0 * e0, d1 = e1 * e1, d2 = e2 * e2;
    float A0 = fmaf(ALPHA_C, d0 + d1 + TAU2_C, 1.0f);
    float A1 = fmaf(ALPHA_C, d0 + d1 + d2 + TAU2_C, 1.0f);
    float A2 = fmaf(ALPHA_C, d1 + d2 + TAU2_C, 1.0f);
    float p01 = A0 * A1, p12 = A1 * A2, p02 = A0 * A2;
    float p = p01 * A2;
    float r;
    asm("rcp.approx.f32 %0, %1;" : "=f"(r) : "f"(p));
    r = r * fmaf(-p, r, 2.0f);
    s0 = r * p12; s1 = r * p02; s2 = r * p01;
}

__device__ __forceinline__ void gbar(unsigned* ep) {
    __syncthreads();
    if (threadIdx.x == 0) {
        unsigned target = ++(*ep);
        unsigned prev = atomicAdd(&g_bar_cnt, 1u);
        if (prev == NBLK - 1) {
            g_bar_cnt = 0u;
            __threadfence();
            atomicExch(&g_bar_epoch, target);
        } else {
            while (*((volatile unsigned*)&g_bar_epoch) < target) { }
            __threadfence();
        }
    }
    __syncthreads();
}

// ------------------------------ kernels ------------------------------------
__global__ void tables_kernel() {
    int j = threadIdx.x;                       // 1024 threads
    float s, c;
    sincospif(-(float)j * (1.0f / 512.0f), &s, &c);
    g_tw1k[j] = make_float2(c, s);
    sincospif(-(float)j * (1.0f / 524288.0f), &s, &c);
    g_twfn[j] = make_float2(c, s);
    if (j == 0) { g_bar_cnt = 0u; g_bar_epoch = 0u; }
}

// 1024-pt smem FFT core: 5 radix-4 Stockham stages, ping<->pong.
// Data laid out as TA columns of CSTR float2 with swz() index mapping.
__device__ __forceinline__ void fft1k_smem(float2* p0, float2* p1,
                                           const float2* s1k, int tid) {
#pragma unroll
    for (int p = 0; p < 5; p++) {
        const int s = 1 << (2 * p);
        float2* pin  = (p & 1) ? p1 : p0;
        float2* pout = (p & 1) ? p0 : p1;
#pragma unroll
        for (int jj = 0; jj < 4; jj++) {
            int w = tid + jj * FTHR;
            int col = w >> 8, t = w & 255;
            float2* cb = pin + col * CSTR;
            float2 a = cb[swz(t)];
            float2 b = cb[swz(t + 256)];
            float2 c = cb[swz(t + 512)];
            float2 d = cb[swz(t + 768)];
            int q = t & (s - 1);
            int ps = t - q;
            float2 w1 = s1k[ps], w2 = s1k[2 * ps], w3 = s1k[3 * ps];
            float apcx = a.x + c.x, apcy = a.y + c.y;
            float amcx = a.x - c.x, amcy = a.y - c.y;
            float bpdx = b.x + d.x, bpdy = b.y + d.y;
            float bmdx = b.x - d.x, bmdy = b.y - d.y;
            int ob = t + 3 * ps;
            float2* ob_ = pout + col * CSTR;
            ob_[swz(ob)]         = make_float2(apcx + bpdx, apcy + bpdy);
            ob_[swz(ob + s)]     = cmulf(amcx + bmdy, amcy - bmdx, w1);
            ob_[swz(ob + 2 * s)] = cmulf(apcx - bpdx, apcy - bpdy, w2);
            ob_[swz(ob + 3 * s)] = cmulf(amcx - bmdy, amcy + bmdx, w3);
        }
        __syncthreads();
    }
}

// Step 1: FFT over b (stride-1024 direction) + inter twiddle e^{-2pi i ac/2^20}.
// xreal != 0: src = real x, dst = g_bufB. else: src = g_bufB+boff, dst = g_bufA+boff.
__global__ void __launch_bounds__(FTHR, 1) fft_s1(const float* __restrict__ xreal) {
    extern __shared__ float2 smemf[];
    float2* p0  = smemf;
    float2* p1  = p0 + TA * CSTR;
    float2* s1k = p1 + TA * CSTR;
    float2* sfn = s1k + 1024;
    const int tid = threadIdx.x;
    const int a0  = blockIdx.x * TA;
    const long boff = (long)blockIdx.y * T_N;

    for (int i = tid; i < 1024; i += FTHR) { s1k[i] = g_tw1k[i]; sfn[i] = g_twfn[i]; }

    if (xreal) {
#pragma unroll
        for (int jj = 0; jj < 16; jj++) {
            int e = tid + jj * FTHR;
            int al = e & 7, b = e >> 3;
            p0[al * CSTR + swz(b)] = make_float2(xreal[a0 + al + (b << 10)], 0.0f);
        }
    } else {
        const float2* __restrict__ src = g_bufB + boff;
#pragma unroll
        for (int jj = 0; jj < 16; jj++) {
            int e = tid + jj * FTHR;
            int al = e & 7, b = e >> 3;
            p0[al * CSTR + swz(b)] = src[a0 + al + (b << 10)];
        }
    }
    __syncthreads();

    fft1k_smem(p0, p1, s1k, tid);       // result in p1 (5 stages, odd)

    float2* dst = xreal ? g_bufB : (g_bufA + boff);
#pragma unroll
    for (int jj = 0; jj < 16; jj++) {
        int e = tid + jj * FTHR;
        int al = e & 7, c = e >> 3;
        int a = a0 + al;
        float2 y = p1[al * CSTR + swz(c)];
        int prod = a * c;               // < 2^20
        float2 w = cmul2(s1k[prod >> 10], sfn[prod & 1023]);
        dst[(c << 10) + a] = cmul2(y, w);
    }
}

// Step 2: FFT over a (contiguous direction), transposed write.
// mode 0: src g_bufB -> complex dst g_bufA. mode 1: src g_bufA+boff -> real out.
__global__ void __launch_bounds__(FTHR, 1) fft_s2(int mode, float* __restrict__ outp) {
    extern __shared__ float2 smemf[];
    float2* p0  = smemf;
    float2* p1  = p0 + TA * CSTR;
    float2* s1k = p1 + TA * CSTR;
    const int tid = threadIdx.x;
    const int c0  = blockIdx.x * TA;
    const long boff = (long)blockIdx.y * T_N;

    for (int i = tid; i < 1024; i += FTHR) s1k[i] = g_tw1k[i];

    const float2* __restrict__ src = (mode ? g_bufA : g_bufB) + boff;
#pragma unroll
    for (int jj = 0; jj < 16; jj++) {
        int e = tid + jj * FTHR;
        int r = e >> 10, a = e & 1023;
        p0[r * CSTR + swz(a)] = src[(long)c0 * 1024 + e];
    }
    __syncthreads();

    fft1k_smem(p0, p1, s1k, tid);       // result in p1

    if (mode == 0) {
        float2* dst = g_bufA + boff;
#pragma unroll
        for (int jj = 0; jj < 16; jj++) {
            int e = tid + jj * FTHR;
            int cl = e & 7, d = e >> 3;
            dst[(d << 10) + c0 + cl] = p1[cl * CSTR + swz(d)];
        }
    } else {
        float* dst = outp + boff;
        const float invT = 1.0f / (float)T_N;
#pragma unroll
        for (int jj = 0; jj < 16; jj++) {
            int e = tid + jj * FTHR;
            int cl = e & 7, d = e >> 3;
            dst[(d << 10) + c0 + cl] = p1[cl * CSTR + swz(d)].x * invT;
        }
    }
}

// ------------------------- persistent VMD loop -----------------------------
template <int EPT>
__device__ __forceinline__ void vmd_impl(const float* __restrict__ om_init) {
    extern __shared__ float sraw[];
    float2* lamA = (float2*)sraw;
    float2* lamB = lamA + CHUNK;
    float*  red  = (float*)(lamB + CHUNK);

    const int tid  = threadIdx.x;
    const int blk  = blockIdx.x;
    const int base = blk * CHUNK + tid;
    const float invT = 1.0f / (float)T_N;
    const float fstep = (float)NTHR * invT;
    const float fbase = (float)base * invT - 0.5f;

    float2 fh[EPT];
#pragma unroll
    for (int j = 0; j < EPT; j++) {
        int i = base + j * NTHR;
        fh[j] = g_bufA[(i + T_HALF) & T_MASK];
        lamA[tid + j * NTHR] = make_float2(0.0f, 0.0f);
    }

    float om0 = om_init[0], om1 = om_init[1], om2 = om_init[2];
    float op0 = om0, op1 = om1, op2 = om2;
    unsigned epoch = 0;
    float fo0 = om0, fo1 = om1, fo2 = om2;
    int fpar = 1;
    bool fin = false;

    for (int n = 0; n < 50 && !fin; n++) {
        float2* lamC = (n & 1) ? lamB : lamA;
        float2* lamN = (n & 1) ? lamA : lamB;
        const bool chk = (n > 0) && (n % 10 == 0);
        const int par = n & 1;

        float acc[8] = {0, 0, 0, 0, 0, 0, 0, 0};

#pragma unroll
        for (int j = 0; j < EPT; j++) {
            int idx = tid + j * NTHR;
            float f = fbase + (float)j * fstep;

            float s0, s1, s2;
            mode_scales(f, om0, om1, om2, s0, s1, s2);

            float2 lm = lamC[idx];
            float cr = fmaf(-0.5f, lm.x, fh[j].x);
            float ci = fmaf(-0.5f, lm.y, fh[j].y);
            float m2 = fmaf(cr, cr, ci * ci);

            float q0 = s0 * s0 * m2, q1 = s1 * s1 * m2, q2 = s2 * s2 * m2;
            acc[0] = fmaf(f, q0, acc[0]);
            acc[1] = fmaf(f, q1, acc[1]);
            acc[2] = fmaf(f, q2, acc[2]);
            acc[3] += q0; acc[4] += q1; acc[5] += q2;

            if (chk) {
                float s0p, s1p, s2p;
                mode_scales(f, op0, op1, op2, s0p, s1p, s2p);
                float2 lp = lamN[idx];
                float cpr = fmaf(-0.5f, lp.x, fh[j].x);
                float cpi = fmaf(-0.5f, lp.y, fh[j].y);
                float er0 = cr * s0 - cpr * s0p, ei0 = ci * s0 - cpi * s0p;
                float er1 = cr * s1 - cpr * s1p, ei1 = ci * s1 - cpi * s1p;
                float er2 = cr * s2 - cpr * s2p, ei2 = ci * s2 - cpi * s2p;
                acc[6] += er0 * er0 + ei0 * ei0 + er1 * er1 + ei1 * ei1
                        + er2 * er2 + ei2 * ei2;
                float m2p = cpr * cpr + cpi * cpi;
                acc[7] = fmaf(m2p, s0p * s0p + s1p * s1p + s2p * s2p, acc[7]);
            }

            float ss = s0 + s1 + s2;
            float ur = fmaf(cr, ss, -fh[j].x);
            float ui = fmaf(ci, ss, -fh[j].y);
            lamN[idx] = make_float2(fmaf(TAU_C, ur, lm.x), fmaf(TAU_C, ui, lm.y));
        }

        unsigned wid = tid >> 5, lane = tid & 31;
#pragma unroll
        for (int k = 0; k < 8; k++) {
            float v = acc[k];
#pragma unroll
            for (int o = 16; o > 0; o >>= 1) v += __shfl_down_sync(0xffffffffu, v, o);
            if (lane == 0) red[wid * 8 + k] = v;
        }
        __syncthreads();
        if (tid < 8) {
            float s = 0.0f;
#pragma unroll
            for (int w = 0; w < 16; w++) s += red[w * 8 + tid];
            g_part[par * NBLK * 8 + blk * 8 + tid] = s;
            __threadfence();
        }

        gbar(&epoch);

        if (tid < 8) {
            float s = 0.0f;
            const float* pp = g_part + par * NBLK * 8 + tid;
            for (int b = 0; b < NBLK; b++) s += __ldcg(pp + b * 8);
            red[tid] = s;
        }
        __syncthreads();
        float wn0 = red[0] / red[3];
        float wn1 = red[1] / red[4];
        float wn2 = red[2] / red[5];
        bool brk = false;
        if (chk) {
            float ud = red[6] / red[7];
            float od = (fabsf(wn0 - wn2) + fabsf(wn1 - wn0) + fabsf(wn2 - wn1)) * (1.0f / 3.0f);
            brk = (ud < TOL_C) && (od < TOL_C);
        }
        __syncthreads();

        if (brk) {
            fo0 = om0; fo1 = om1; fo2 = om2;
            fpar = n & 1;
            fin = true;
        } else {
            op0 = om0; op1 = om1; op2 = om2;
            om0 = wn0; om1 = wn1; om2 = wn2;
        }
    }
    if (!fin) { fo0 = op0; fo1 = op1; fo2 = op2; fpar = 1; }

    float2* lamF = fpar ? lamB : lamA;
#pragma unroll
    for (int j = 0; j < EPT; j++) {
        int idx = tid + j * NTHR;
        int i = base + j * NTHR;
        float f = fbase + (float)j * fstep;
        float s0, s1, s2;
        mode_scales(f, fo0, fo1, fo2, s0, s1, s2);
        float2 lm = lamF[idx];
        float cr = fmaf(-0.5f, lm.x, fh[j].x);
        float ci = fmaf(-0.5f, lm.y, fh[j].y);
        int jd = (i + T_HALF) & T_MASK;
        g_bufB[jd]           = make_float2(cr * s0, -(ci * s0));
        g_bufB[T_N + jd]     = make_float2(cr * s1, -(ci * s1));
        g_bufB[2 * T_N + jd] = make_float2(cr * s2, -(ci * s2));
    }
}

__global__ void __launch_bounds__(NTHR, 1) vmd_loop(const float* __restrict__ om_init) {
    if (blockIdx.x < NBLK - 1) vmd_impl<EPT_F>(om_init);
    else                       vmd_impl<EPT_T>(om_init);
}

// ------------------------------ launcher -----------------------------------
extern "C" void kernel_launch(void* const* d_in, const int* in_sizes, int n_in,
                              void* d_out, int out_size) {
    (void)in_sizes; (void)n_in; (void)out_size;
    const float* x  = (const float*)d_in[0];
    const float* om = (const float*)d_in[1];
    float* out = (float*)d_out;

    static int inited = 0;
    if (!inited) {
        cudaFuncSetAttribute((const void*)vmd_loop,
                             cudaFuncAttributeMaxDynamicSharedMemorySize, VSMEM);
        cudaFuncSetAttribute((const void*)fft_s1,
                             cudaFuncAttributeMaxDynamicSharedMemorySize, F_SMEM);
        cudaFuncSetAttribute((const void*)fft_s2,
                             cudaFuncAttributeMaxDynamicSharedMemorySize, F_SMEM);
        inited = 1;
    }

    tables_kernel<<<1, 1024>>>();

    // FFT(x): x -> bufB (S1), bufB -> bufA (S2)
    fft_s1<<<dim3(FBLK, 1), FTHR, F_SMEM>>>(x);
    fft_s2<<<dim3(FBLK, 1), FTHR, F_SMEM>>>(0, nullptr);

    // 50 VMD iterations; writes conj(ifftshift(u_hat)) for 3 modes into bufB.
    vmd_loop<<<NBLK, NTHR, VSMEM>>>(om);

    // FFT of the 3 modes: bufB -> bufA (S1), bufA -> out real (S2)
    fft_s1<<<dim3(FBLK, 3), FTHR, F_SMEM>>>(nullptr);
    fft_s2<<<dim3(FBLK, 3), FTHR, F_SMEM>>>(1, out);
}

// round 5
// speedup vs baseline: 1.6917x; 1.2374x over previous
#include <cuda_runtime.h>
#include <cstdint>

// ---------------------------------------------------------------------------
// VMD on GB300, round 4:
//   - vmd_loop: lambda in REGISTERS, f32x2 packed math, 49 iterations,
//               parallel 3-stage reduction, grid barrier over 128 blocks
//   - FFT: four-step 1024x1024, per-block twiddle tables
// ---------------------------------------------------------------------------

#define T_N     (1 << 20)
#define T_MASK  (T_N - 1)
#define T_HALF  (1 << 19)

#define NBLK    128
#define NTHR    512
#define EPT     16
#define CHUNK   (NTHR * EPT)          // 8192 elems per block

#define ALPHA_C 2000.0f
#define TAU_C   1e-7f
#define TAU2_C  1e-14f
#define TOL_C   1e-6f

#define VSMEM   (2 * CHUNK * 8 + (16 * 8 + 8) * 4)

// ---- FFT geometry: N = 1024 x 1024 ----
#define TA      8
#define FTHR    512
#define CSTR    1028
#define FBLK    128
#define F_SMEM  ((2 * TA * CSTR + 2 * 1024) * 8)

typedef unsigned long long u64;

// ------------------------- device global scratch ---------------------------
__device__ float2   g_bufA[3 * T_N];
__device__ float2   g_bufB[3 * T_N];
__device__ float    g_part[2 * NBLK * 8];
__device__ unsigned g_bar_cnt;
__device__ unsigned g_bar_epoch;

// --------------------------- f32x2 helpers ---------------------------------
__device__ __forceinline__ u64 f2pk(float lo, float hi) {
    u64 d; asm("mov.b64 %0,{%1,%2};" : "=l"(d) : "f"(lo), "f"(hi)); return d;
}
__device__ __forceinline__ void f2up(u64 v, float& lo, float& hi) {
    asm("mov.b64 {%0,%1},%2;" : "=f"(lo), "=f"(hi) : "l"(v));
}
__device__ __forceinline__ u64 f2spl(float x) { return f2pk(x, x); }
__device__ __forceinline__ u64 f2add(u64 a, u64 b) {
    u64 d; asm("add.rn.f32x2 %0,%1,%2;" : "=l"(d) : "l"(a), "l"(b)); return d;
}
__device__ __forceinline__ u64 f2mul(u64 a, u64 b) {
    u64 d; asm("mul.rn.f32x2 %0,%1,%2;" : "=l"(d) : "l"(a), "l"(b)); return d;
}
__device__ __forceinline__ u64 f2fma(u64 a, u64 b, u64 c) {
    u64 d; asm("fma.rn.f32x2 %0,%1,%2,%3;" : "=l"(d) : "l"(a), "l"(b), "l"(c)); return d;
}

// packed mode scales for an element pair: s_k = 1/(1+alpha*denom_k), one rcp.
__device__ __forceinline__ void msc2(u64 fp, u64 nw0, u64 nw1, u64 nw2,
                                     u64 CAL, u64 CT2, u64 CONE,
                                     u64& s0, u64& s1, u64& s2) {
    u64 e0 = f2add(fp, nw0), e1 = f2add(fp, nw1), e2 = f2add(fp, nw2);
    u64 d0 = f2mul(e0, e0), d1 = f2mul(e1, e1), d2 = f2mul(e2, e2);
    u64 t01 = f2add(d0, d1), t12 = f2add(d1, d2);
    u64 t012 = f2add(t01, d2);
    u64 A0 = f2fma(CAL, f2add(t01, CT2), CONE);
    u64 A1 = f2fma(CAL, f2add(t012, CT2), CONE);
    u64 A2 = f2fma(CAL, f2add(t12, CT2), CONE);
    u64 p01 = f2mul(A0, A1), p12 = f2mul(A1, A2), p02 = f2mul(A0, A2);
    u64 p = f2mul(p01, A2);
    float pa, pb; f2up(p, pa, pb);
    float P = pa * pb, r;
    asm("rcp.approx.f32 %0,%1;" : "=f"(r) : "f"(P));
    r = r * fmaf(-P, r, 2.0f);
    u64 rp = f2pk(r * pb, r * pa);               // (1/pa, 1/pb)
    s0 = f2mul(rp, p12); s1 = f2mul(rp, p02); s2 = f2mul(rp, p01);
}

__device__ __forceinline__ float2 cmulf(float ux, float uy, float2 w) {
    return make_float2(fmaf(ux, w.x, -uy * w.y), fmaf(ux, w.y, uy * w.x));
}
__device__ __forceinline__ float2 cmul2(float2 a, float2 b) {
    return make_float2(fmaf(a.x, b.x, -a.y * b.y), fmaf(a.x, b.y, a.y * b.x));
}
__device__ __forceinline__ int swz(int m) {
    int h = (m >> 4) & 15;
    return m ^ (h ^ ((h << 1) & 15));
}

__device__ __forceinline__ void gbar(unsigned* ep) {
    __syncthreads();
    if (threadIdx.x == 0) {
        unsigned target = ++(*ep);
        unsigned prev = atomicAdd(&g_bar_cnt, 1u);
        if (prev == NBLK - 1) {
            g_bar_cnt = 0u;
            __threadfence();
            atomicExch(&g_bar_epoch, target);
        } else {
            while (*((volatile unsigned*)&g_bar_epoch) < target) { }
            __threadfence();
        }
    }
    __syncthreads();
}

// ------------------------------ kernels ------------------------------------
__global__ void init_kernel() { g_bar_cnt = 0u; g_bar_epoch = 0u; }

// 1024-pt smem FFT core: 5 radix-4 Stockham stages, ping<->pong.
__device__ __forceinline__ void fft1k_smem(float2* p0, float2* p1,
                                           const float2* s1k, int tid) {
#pragma unroll
    for (int p = 0; p < 5; p++) {
        const int s = 1 << (2 * p);
        float2* pin  = (p & 1) ? p1 : p0;
        float2* pout = (p & 1) ? p0 : p1;
#pragma unroll
        for (int jj = 0; jj < 4; jj++) {
            int w = tid + jj * FTHR;
            int col = w >> 8, t = w & 255;
            float2* cb = pin + col * CSTR;
            float2 a = cb[swz(t)];
            float2 b = cb[swz(t + 256)];
            float2 c = cb[swz(t + 512)];
            float2 d = cb[swz(t + 768)];
            int q = t & (s - 1);
            int ps = t - q;
            float2 w1 = s1k[ps], w2 = s1k[2 * ps], w3 = s1k[3 * ps];
            float apcx = a.x + c.x, apcy = a.y + c.y;
            float amcx = a.x - c.x, amcy = a.y - c.y;
            float bpdx = b.x + d.x, bpdy = b.y + d.y;
            float bmdx = b.x - d.x, bmdy = b.y - d.y;
            int ob = t + 3 * ps;
            float2* ob_ = pout + col * CSTR;
            ob_[swz(ob)]         = make_float2(apcx + bpdx, apcy + bpdy);
            ob_[swz(ob + s)]     = cmulf(amcx + bmdy, amcy - bmdx, w1);
            ob_[swz(ob + 2 * s)] = cmulf(apcx - bpdx, apcy - bpdy, w2);
            ob_[swz(ob + 3 * s)] = cmulf(amcx - bmdy, amcy + bmdx, w3);
        }
        __syncthreads();
    }
}

// Step 1: FFT over b (stride-1024) + inter twiddle e^{-2pi i ac/2^20}.
__global__ void __launch_bounds__(FTHR, 1) fft_s1(const float* __restrict__ xreal) {
    extern __shared__ float2 smemf[];
    float2* p0  = smemf;
    float2* p1  = p0 + TA * CSTR;
    float2* s1k = p1 + TA * CSTR;
    float2* sfn = s1k + 1024;
    const int tid = threadIdx.x;
    const int a0  = blockIdx.x * TA;
    const long boff = (long)blockIdx.y * T_N;

    for (int i = tid; i < 1024; i += FTHR) {
        float s, c;
        sincospif(-(float)i * (1.0f / 512.0f), &s, &c);
        s1k[i] = make_float2(c, s);
        sincospif(-(float)i * (1.0f / 524288.0f), &s, &c);
        sfn[i] = make_float2(c, s);
    }

    if (xreal) {
#pragma unroll
        for (int jj = 0; jj < 16; jj++) {
            int e = tid + jj * FTHR;
            int al = e & 7, b = e >> 3;
            p0[al * CSTR + swz(b)] = make_float2(xreal[a0 + al + (b << 10)], 0.0f);
        }
    } else {
        const float2* __restrict__ src = g_bufB + boff;
#pragma unroll
        for (int jj = 0; jj < 16; jj++) {
            int e = tid + jj * FTHR;
            int al = e & 7, b = e >> 3;
            p0[al * CSTR + swz(b)] = src[a0 + al + (b << 10)];
        }
    }
    __syncthreads();

    fft1k_smem(p0, p1, s1k, tid);

    float2* dst = xreal ? g_bufB : (g_bufA + boff);
#pragma unroll
    for (int jj = 0; jj < 16; jj++) {
        int e = tid + jj * FTHR;
        int al = e & 7, c = e >> 3;
        int a = a0 + al;
        float2 y = p1[al * CSTR + swz(c)];
        int prod = a * c;
        float2 w = cmul2(s1k[prod >> 10], sfn[prod & 1023]);
        dst[(c << 10) + a] = cmul2(y, w);
    }
}

// Step 2: FFT over a (contiguous), transposed write.
__global__ void __launch_bounds__(FTHR, 1) fft_s2(int mode, float* __restrict__ outp) {
    extern __shared__ float2 smemf[];
    float2* p0  = smemf;
    float2* p1  = p0 + TA * CSTR;
    float2* s1k = p1 + TA * CSTR;
    const int tid = threadIdx.x;
    const int c0  = blockIdx.x * TA;
    const long boff = (long)blockIdx.y * T_N;

    for (int i = tid; i < 1024; i += FTHR) {
        float s, c;
        sincospif(-(float)i * (1.0f / 512.0f), &s, &c);
        s1k[i] = make_float2(c, s);
    }

    const float2* __restrict__ src = (mode ? g_bufA : g_bufB) + boff;
#pragma unroll
    for (int jj = 0; jj < 16; jj++) {
        int e = tid + jj * FTHR;
        int r = e >> 10, a = e & 1023;
        p0[r * CSTR + swz(a)] = src[(long)c0 * 1024 + e];
    }
    __syncthreads();

    fft1k_smem(p0, p1, s1k, tid);

    if (mode == 0) {
        float2* dst = g_bufA + boff;
#pragma unroll
        for (int jj = 0; jj < 16; jj++) {
            int e = tid + jj * FTHR;
            int cl = e & 7, d = e >> 3;
            dst[(d << 10) + c0 + cl] = p1[cl * CSTR + swz(d)];
        }
    } else {
        float* dst = outp + boff;
        const float invT = 1.0f / (float)T_N;
#pragma unroll
        for (int jj = 0; jj < 16; jj++) {
            int e = tid + jj * FTHR;
            int cl = e & 7, d = e >> 3;
            dst[(d << 10) + c0 + cl] = p1[cl * CSTR + swz(d)].x * invT;
        }
    }
}

// ------------------------- persistent VMD loop -----------------------------
__global__ void __launch_bounds__(NTHR, 1) vmd_loop(const float* __restrict__ om_init) {
    extern __shared__ u64 svm[];
    u64*   lamP = svm;                 // lambda^(n-1) snapshot (saved at n%10==9)
    u64*   lamS = svm + CHUNK;         // lambda^(n)   snapshot (saved at chk)
    float* red  = (float*)(svm + 2 * CHUNK);   // 16 warps x 8
    float* red2 = red + 16 * 8;                // 8 totals

    const int tid  = threadIdx.x;
    const int blk  = blockIdx.x;
    const int base = blk * CHUNK + tid;
    const float invT = 1.0f / (float)T_N;
    const float fstep = (float)NTHR * invT;
    const float fbase = (float)base * invT - 0.5f;

    const u64 CNH  = f2spl(-0.5f);
    const u64 CAL  = f2spl(ALPHA_C);
    const u64 CT2  = f2spl(TAU2_C);
    const u64 CONE = f2spl(1.0f);
    const u64 CTAU = f2spl(TAU_C);
    const u64 CNTA = f2spl(-TAU_C);

    u64 fh[EPT];
    u64 lam[EPT];
#pragma unroll
    for (int j = 0; j < EPT; j++) {
        int i = base + j * NTHR;
        float2 v = g_bufA[(i + T_HALF) & T_MASK];
        fh[j] = f2pk(v.x, v.y);
        lam[j] = 0ull;
    }

    float om0 = om_init[0], om1 = om_init[1], om2 = om_init[2];
    float op0 = om0, op1 = om1, op2 = om2;
    float fo0 = om0, fo1 = om1, fo2 = om2;
    unsigned epoch = 0;
    bool fin = false, useS = false;
    const unsigned wid = tid >> 5, lane = tid & 31;

    for (int n = 0; n < 49 && !fin; n++) {
        const bool chk  = (n > 0) && (n % 10 == 0);
        const bool savP = (n % 10 == 9);
        const int  par  = n & 1;

        const u64 nw0 = f2spl(-om0), nw1 = f2spl(-om1), nw2 = f2spl(-om2);
        const u64 no0 = f2spl(-op0), no1 = f2spl(-op1), no2 = f2spl(-op2);

        u64 af0 = 0, af1 = 0, af2 = 0, ap0 = 0, ap1 = 0, ap2 = 0;
        u64 a6 = 0, a7 = 0;

#pragma unroll
        for (int jp = 0; jp < EPT / 2; jp++) {
            const int j0 = 2 * jp, j1 = j0 + 1;
            const int idx0 = tid + j0 * NTHR, idx1 = tid + j1 * NTHR;
            float fa = fbase + (float)j0 * fstep;
            u64 fp = f2pk(fa, fa + fstep);

            u64 s0, s1, s2;
            msc2(fp, nw0, nw1, nw2, CAL, CT2, CONE, s0, s1, s2);

            u64 cpa = f2fma(lam[j0], CNH, fh[j0]);   // (cr,ci) elem a
            u64 cpb = f2fma(lam[j1], CNH, fh[j1]);
            float xa, xb;
            u64 sqa = f2mul(cpa, cpa); f2up(sqa, xa, xb); float m2a = xa + xb;
            u64 sqb = f2mul(cpb, cpb); f2up(sqb, xa, xb); float m2b = xa + xb;
            u64 m2p = f2pk(m2a, m2b);

            u64 q0 = f2mul(f2mul(s0, s0), m2p);
            u64 q1 = f2mul(f2mul(s1, s1), m2p);
            u64 q2 = f2mul(f2mul(s2, s2), m2p);
            af0 = f2fma(fp, q0, af0); ap0 = f2add(ap0, q0);
            af1 = f2fma(fp, q1, af1); ap1 = f2add(ap1, q1);
            af2 = f2fma(fp, q2, af2); ap2 = f2add(ap2, q2);

            if (chk) {
                u64 t0, t1, t2;
                msc2(fp, no0, no1, no2, CAL, CT2, CONE, t0, t1, t2);
                u64 lpa = lamP[idx0], lpb = lamP[idx1];
                u64 cqa = f2fma(lpa, CNH, fh[j0]);
                u64 cqb = f2fma(lpb, CNH, fh[j1]);
                float s0a, s0b, s1a, s1b, s2a, s2b;
                f2up(s0, s0a, s0b); f2up(s1, s1a, s1b); f2up(s2, s2a, s2b);
                float t0a, t0b, t1a, t1b, t2a, t2b;
                f2up(t0, t0a, t0b); f2up(t1, t1a, t1b); f2up(t2, t2a, t2b);
                u64 da;
                da = f2fma(cpa, f2spl(s0a), f2mul(cqa, f2spl(-t0a))); a6 = f2fma(da, da, a6);
                da = f2fma(cpa, f2spl(s1a), f2mul(cqa, f2spl(-t1a))); a6 = f2fma(da, da, a6);
                da = f2fma(cpa, f2spl(s2a), f2mul(cqa, f2spl(-t2a))); a6 = f2fma(da, da, a6);
                da = f2fma(cpb, f2spl(s0b), f2mul(cqb, f2spl(-t0b))); a6 = f2fma(da, da, a6);
                da = f2fma(cpb, f2spl(s1b), f2mul(cqb, f2spl(-t1b))); a6 = f2fma(da, da, a6);
                da = f2fma(cpb, f2spl(s2b), f2mul(cqb, f2spl(-t2b))); a6 = f2fma(da, da, a6);
                u64 qq = f2mul(cqa, cqa); f2up(qq, xa, xb); float m2pa = xa + xb;
                qq = f2mul(cqb, cqb);     f2up(qq, xa, xb); float m2pb = xa + xb;
                u64 ssq = f2fma(t0, t0, f2fma(t1, t1, f2mul(t2, t2)));
                a7 = f2fma(f2pk(m2pa, m2pb), ssq, a7);
                lamS[idx0] = lam[j0]; lamS[idx1] = lam[j1];   // snapshot lam^(n)
            }
            if (savP) { lamP[idx0] = lam[j0]; lamP[idx1] = lam[j1]; }

            // lambda update: lam += tau*(c*ss) - tau*fh
            u64 ssp = f2add(f2add(s0, s1), s2);
            float ssa, ssb; f2up(ssp, ssa, ssb);
            lam[j0] = f2fma(CTAU, f2mul(cpa, f2spl(ssa)), lam[j0]);
            lam[j0] = f2fma(CNTA, fh[j0], lam[j0]);
            lam[j1] = f2fma(CTAU, f2mul(cpb, f2spl(ssb)), lam[j1]);
            lam[j1] = f2fma(CNTA, fh[j1], lam[j1]);
        }

        // ---- stage 1: per-warp shuffle reduce of 8 scalars ----
        float hv[8];
        { float a, b;
          f2up(af0, a, b); hv[0] = a + b;  f2up(af1, a, b); hv[1] = a + b;
          f2up(af2, a, b); hv[2] = a + b;  f2up(ap0, a, b); hv[3] = a + b;
          f2up(ap1, a, b); hv[4] = a + b;  f2up(ap2, a, b); hv[5] = a + b;
          f2up(a6, a, b);  hv[6] = a + b;  f2up(a7, a, b);  hv[7] = a + b; }
#pragma unroll
        for (int k = 0; k < 8; k++) {
            float v = hv[k];
#pragma unroll
            for (int o = 16; o > 0; o >>= 1) v += __shfl_down_sync(0xffffffffu, v, o);
            if (lane == 0) red[wid * 8 + k] = v;
        }
        __syncthreads();

        // ---- stage 2: warp k reduces 16 warp-partials of acc k ----
        if (wid < 8) {
            float v = (lane < 16) ? red[lane * 8 + wid] : 0.0f;
#pragma unroll
            for (int o = 16; o > 0; o >>= 1) v += __shfl_down_sync(0xffffffffu, v, o);
            if (lane == 0) {
                g_part[par * NBLK * 8 + blk * 8 + wid] = v;
                __threadfence();
            }
        }

        gbar(&epoch);

        // ---- stage 3: warp k sums 128 block-partials of acc k ----
        if (wid < 8) {
            const float* pp = g_part + par * NBLK * 8 + wid;
            float v = __ldcg(pp + lane * 8) + __ldcg(pp + (lane + 32) * 8)
                    + __ldcg(pp + (lane + 64) * 8) + __ldcg(pp + (lane + 96) * 8);
#pragma unroll
            for (int o = 16; o > 0; o >>= 1) v += __shfl_down_sync(0xffffffffu, v, o);
            if (lane == 0) red2[wid] = v;
        }
        __syncthreads();

        float wn0 = red2[0] / red2[3];
        float wn1 = red2[1] / red2[4];
        float wn2 = red2[2] / red2[5];
        bool brk = false;
        if (chk) {
            float ud = red2[6] / red2[7];
            float od = (fabsf(wn0 - wn2) + fabsf(wn1 - wn0) + fabsf(wn2 - wn1)) * (1.0f / 3.0f);
            brk = (ud < TOL_C) && (od < TOL_C);
        }
        __syncthreads();

        if (brk) {
            fin = true; useS = true;
            fo0 = om0; fo1 = om1; fo2 = om2;
        } else {
            op0 = om0; op1 = om1; op2 = om2;
            om0 = wn0; om1 = wn1; om2 = wn2;
        }
    }
    if (!fin) { fo0 = om0; fo1 = om1; fo2 = om2; }   // omega^(49), lam regs = lam^(49)

    // ---- final u_hat: write conj(ifftshift(u_k)) into g_bufB[k*T + ...] ----
    const u64 nf0 = f2spl(-fo0), nf1 = f2spl(-fo1), nf2 = f2spl(-fo2);
#pragma unroll
    for (int jp = 0; jp < EPT / 2; jp++) {
        const int j0 = 2 * jp, j1 = j0 + 1;
        const int idx0 = tid + j0 * NTHR, idx1 = tid + j1 * NTHR;
        float fa = fbase + (float)j0 * fstep;
        u64 fp = f2pk(fa, fa + fstep);
        u64 s0, s1, s2;
        msc2(fp, nf0, nf1, nf2, CAL, CT2, CONE, s0, s1, s2);
        float s0a, s0b, s1a, s1b, s2a, s2b;
        f2up(s0, s0a, s0b); f2up(s1, s1a, s1b); f2up(s2, s2a, s2b);

        u64 lva = useS ? lamS[idx0] : lam[j0];
        u64 lvb = useS ? lamS[idx1] : lam[j1];
        u64 cpa = f2fma(lva, CNH, fh[j0]);
        u64 cpb = f2fma(lvb, CNH, fh[j1]);
        float cr, ci;

        f2up(cpa, cr, ci);
        int jd = ((base + j0 * NTHR) + T_HALF) & T_MASK;
        g_bufB[jd]           = make_float2(cr * s0a, -(ci * s0a));
        g_bufB[T_N + jd]     = make_float2(cr * s1a, -(ci * s1a));
        g_bufB[2 * T_N + jd] = make_float2(cr * s2a, -(ci * s2a));

        f2up(cpb, cr, ci);
        jd = ((base + j1 * NTHR) + T_HALF) & T_MASK;
        g_bufB[jd]           = make_float2(cr * s0b, -(ci * s0b));
        g_bufB[T_N + jd]     = make_float2(cr * s1b, -(ci * s1b));
        g_bufB[2 * T_N + jd] = make_float2(cr * s2b, -(ci * s2b));
    }
}

// ------------------------------ launcher -----------------------------------
extern "C" void kernel_launch(void* const* d_in, const int* in_sizes, int n_in,
                              void* d_out, int out_size) {
    (void)in_sizes; (void)n_in; (void)out_size;
    const float* x  = (const float*)d_in[0];
    const float* om = (const float*)d_in[1];
    float* out = (float*)d_out;

    cudaFuncSetAttribute((const void*)vmd_loop,
                         cudaFuncAttributeMaxDynamicSharedMemorySize, VSMEM);
    cudaFuncSetAttribute((const void*)fft_s1,
                         cudaFuncAttributeMaxDynamicSharedMemorySize, F_SMEM);
    cudaFuncSetAttribute((const void*)fft_s2,
                         cudaFuncAttributeMaxDynamicSharedMemorySize, F_SMEM);

    init_kernel<<<1, 1>>>();

    // FFT(x): x -> bufB (S1), bufB -> bufA (S2)
    fft_s1<<<dim3(FBLK, 1), FTHR, F_SMEM>>>(x);
    fft_s2<<<dim3(FBLK, 1), FTHR, F_SMEM>>>(0, nullptr);

    // 49 VMD iterations; writes conj(ifftshift(u_hat)) for 3 modes into bufB.
    vmd_loop<<<NBLK, NTHR, VSMEM>>>(om);

    // FFT of the 3 modes: bufB -> bufA (S1), bufA -> out real (S2)
    fft_s1<<<dim3(FBLK, 3), FTHR, F_SMEM>>>(nullptr);
    fft_s2<<<dim3(FBLK, 3), FTHR, F_SMEM>>>(1, out);
}